// round 15
// baseline (speedup 1.0000x reference)
#include <cuda_runtime.h>
#include <cuda_fp16.h>
#include <cstdint>

#define D      256
#define TT     9
#define NTYPES 14
#define NSRC   5
#define PMAX   4
#define BM     128
#define E_MAX  131072
#define NBMAX  512
#define NCTA   148

// ---- dynamic SMEM layout (bytes) ----
#define SM_XS   0                    // 128 x float4        2048
#define SM_E    2048                 // 128 x int            512
#define SM_TI   2560                 // 128 x int            512
#define SM_W1T  3072                 // 256 x float4        4096
#define SM_B1   7168                 // 256 x float         1024
#define SM_A    8192                 // 128 x 528B         67584
#define SM_SB   75776                // 8 rings x 256k x 64B = 131072 (XOR-swizzled)
#define SM_TOTAL 206848
#define LDAB    528
#define RING    16384                // 256 x 64

__constant__ int   c_base_map[NTYPES] = {0,0,0,1,1,1,2,2,3,4,5,6,7,8};
__constant__ int   c_pcount[TT]       = {2,2,1,1,1,1,3,2,4};
__constant__ float c_scales[TT][PMAX] = {
  {1.f,1e-6f,1.f,1.f},{1.f,1e-6f,1.f,1.f},{1.f,1.f,1.f,1.f},
  {1000.f,1.f,1.f,1.f},{1e-12f,1.f,1.f,1.f},{1e-9f,1.f,1.f,1.f},
  {1.f,1.f,1.f,1.f},{1e-3f,1e-3f,1.f,1.f},{1.f,1.f,1e9f,1.f}
};

// ---- device scratch ----
__device__ int   g_part[NBMAX][TT];
__device__ int   g_bbase[NBMAX][TT];
__device__ int   g_counts[TT];
__device__ int   g_offsets[TT+1];
__device__ int   g_tile_off[TT+1];
__device__ int   g_perm[E_MAX];
__device__ __align__(16) __half g_B[TT][256][256];      // [t][k][n] fp16
__device__ float g_tc[NTYPES][D];
__device__ float g_sc[NSRC][D];
__device__ float g_b2f[TT][D];                          // includes bf
__device__ float g_ts[NTYPES*NSRC][D];                  // combined epilogue table

// ================= PTX helpers =================
__device__ __forceinline__ uint32_t smem_u32(const void* p) {
  uint32_t a;
  asm("{ .reg .u64 t; cvta.to.shared.u64 t, %1; cvt.u32.u64 %0, t; }" : "=r"(a) : "l"(p));
  return a;
}
__device__ __forceinline__ void cp16(uint32_t dst, const void* src) {
  asm volatile("cp.async.cg.shared.global [%0], [%1], 16;" :: "r"(dst), "l"(src) : "memory");
}
__device__ __forceinline__ void ldm_x4(uint32_t* r, uint32_t a) {
  asm volatile("ldmatrix.sync.aligned.m8n8.x4.shared.b16 {%0,%1,%2,%3}, [%4];"
    : "=r"(r[0]),"=r"(r[1]),"=r"(r[2]),"=r"(r[3]) : "r"(a));
}
__device__ __forceinline__ void ldm_x4t(uint32_t* r, uint32_t a) {
  asm volatile("ldmatrix.sync.aligned.m8n8.x4.trans.shared.b16 {%0,%1,%2,%3}, [%4];"
    : "=r"(r[0]),"=r"(r[1]),"=r"(r[2]),"=r"(r[3]) : "r"(a));
}
__device__ __forceinline__ void mma16816(float* c, const uint32_t* a, uint32_t b0, uint32_t b1) {
  asm("mma.sync.aligned.m16n8k16.row.col.f32.f16.f16.f32 "
      "{%0,%1,%2,%3}, {%4,%5,%6,%7}, {%8,%9}, {%0,%1,%2,%3};"
      : "+f"(c[0]),"+f"(c[1]),"+f"(c[2]),"+f"(c[3])
      : "r"(a[0]),"r"(a[1]),"r"(a[2]),"r"(a[3]), "r"(b0),"r"(b1));
}

// ================= launch 0: per-block histogram (4 edges/thread) =================
__global__ void k_hist(const int* __restrict__ type_ids, int E) {
  __shared__ int lh[TT];
  int tid = threadIdx.x, b = blockIdx.x;
  if (tid < TT) lh[tid] = 0;
  __syncthreads();
  int base = (b * 256 + tid) * 4;
  if (base + 3 < E) {
    int4 tv = *(const int4*)&type_ids[base];
    atomicAdd(&lh[c_base_map[tv.x]], 1);
    atomicAdd(&lh[c_base_map[tv.y]], 1);
    atomicAdd(&lh[c_base_map[tv.z]], 1);
    atomicAdd(&lh[c_base_map[tv.w]], 1);
  } else {
    for (int q = 0; q < 4; q++) {
      int e = base + q;
      if (e < E) atomicAdd(&lh[c_base_map[type_ids[e]]], 1);
    }
  }
  __syncthreads();
  if (tid < TT) g_part[b][tid] = lh[tid];
}

// ================= launch 1: fused w2f(8-row blocks) + tables + scan =================
__global__ void k_fused(const float* __restrict__ te, const float* __restrict__ se,
                        const float* __restrict__ b2, const float* __restrict__ Wf,
                        const float* __restrict__ bf, const float* __restrict__ W2,
                        int nb) {
  int bx = blockIdx.x, d = threadIdx.x;
  if (bx < 288) {
    __shared__ float sW2[8][D];
    int t = bx >> 5, kg = bx & 31;
    for (int kk = 0; kk < 8; kk++)
      sW2[kk][d] = W2[(t * D + kg * 8 + kk) * D + d];
    __syncthreads();
    float acc[8];
    #pragma unroll
    for (int kk = 0; kk < 8; kk++) acc[kk] = 0.f;
    const float* wb = Wf + 512 * D + d;
    for (int dp = 0; dp < D; dp++) {
      float wf = wb[dp * D];
      #pragma unroll
      for (int kk = 0; kk < 8; kk++) acc[kk] = fmaf(sW2[kk][dp], wf, acc[kk]);
    }
    #pragma unroll
    for (int kk = 0; kk < 8; kk++)
      g_B[t][kg * 8 + kk][d] = __float2half(acc[kk]);
  } else if (bx < 316) {
    __shared__ float row[D];
    int r = bx - 288;
    const float* src; const float* wbase; float* dst; float acc;
    if (r < NTYPES)             { src = te + r * D;            wbase = Wf;           dst = &g_tc[r][0]; acc = 0.f; }
    else if (r < NTYPES + NSRC) { int s = r - NTYPES; src = se + s * D; wbase = Wf + 256 * D; dst = &g_sc[s][0]; acc = 0.f; }
    else                        { int t = r - NTYPES - NSRC; src = b2 + t * D; wbase = Wf + 512 * D; dst = &g_b2f[t][0]; acc = bf[d]; }
    row[d] = src[d];
    __syncthreads();
    #pragma unroll 8
    for (int k = 0; k < D; k++) acc = fmaf(row[k], wbase[k * D + d], acc);
    dst[d] = acc;
  } else {
    int lane = d & 31, w = d >> 5;
    for (int t = w; t < TT; t += 8) {
      int carry = 0;
      for (int c = 0; c < nb; c += 32) {
        int idx = c + lane;
        int orig = (idx < nb) ? g_part[idx][t] : 0;
        int v = orig;
        #pragma unroll
        for (int sft = 1; sft < 32; sft <<= 1) {
          int u = __shfl_up_sync(0xffffffffu, v, sft);
          if (lane >= sft) v += u;
        }
        if (idx < nb) g_bbase[idx][t] = carry + v - orig;
        carry += __shfl_sync(0xffffffffu, v, 31);
      }
      if (lane == 0) g_counts[t] = carry;
    }
    __syncthreads();
    if (d == 0) {
      int off = 0, toff = 0;
      for (int t = 0; t < TT; t++) {
        g_offsets[t] = off; g_tile_off[t] = toff;
        off += g_counts[t];
        toff += (g_counts[t] + BM - 1) / BM;
      }
      g_offsets[TT] = off; g_tile_off[TT] = toff;
    }
  }
}

// ================= launch 2: scatter (4 edges/thread) + table combine =================
__global__ void k_scatter(const int* __restrict__ type_ids, int E, int nb) {
  int tid = threadIdx.x, b = blockIdx.x;
  if (b >= nb) {
    int r = b - nb, ty = r / NSRC, s = r % NSRC;
    int t = c_base_map[ty];
    g_ts[r][tid] = g_tc[ty][tid] + g_sc[s][tid] + g_b2f[t][tid];
    return;
  }
  __shared__ int lh[TT];
  if (tid < TT) lh[tid] = 0;
  __syncthreads();
  int base = (b * 256 + tid) * 4;
  int tloc[4], lpos[4];
  if (base + 3 < E) {
    int4 tv = *(const int4*)&type_ids[base];
    tloc[0] = c_base_map[tv.x]; tloc[1] = c_base_map[tv.y];
    tloc[2] = c_base_map[tv.z]; tloc[3] = c_base_map[tv.w];
    #pragma unroll
    for (int q = 0; q < 4; q++) lpos[q] = atomicAdd(&lh[tloc[q]], 1);
    #pragma unroll
    for (int q = 0; q < 4; q++)
      g_perm[g_offsets[tloc[q]] + g_bbase[b][tloc[q]] + lpos[q]] = base + q;
  } else {
    for (int q = 0; q < 4; q++) {
      int e = base + q;
      if (e < E) {
        int t = c_base_map[type_ids[e]];
        int lp = atomicAdd(&lh[t], 1);
        g_perm[g_offsets[t] + g_bbase[b][t] + lp] = e;
      }
    }
  }
}

// ================= launch 3: main HMMA kernel =================
// 148 persistent CTAs x 512 threads = 16 warps (2M x 8N), warp tile 64x32.
// Full-item B staged ONCE in XOR-swizzled pitch-64 rings (one per wn column,
// shared by both wm warps; each warp fills half). Mainloop is pure LDSM+MMA:
// zero cp.async, zero wait_group, zero syncs.
// Swizzle: segment c of row r stored at position c ^ ((r>>1)&3); conflict-free
// for all ldmatrix phases (word starts {0,4,...,28}).
__global__ __launch_bounds__(512, 1) void k_main(
    const int* __restrict__ type_ids, const int* __restrict__ source_ids,
    const float* __restrict__ params, const float* __restrict__ W1,
    const float* __restrict__ b1, float* __restrict__ out, int chunk) {
  extern __shared__ char smem[];
  uint32_t sb = smem_u32(smem);
  int tid = threadIdx.x;
  int w = tid >> 5, lane = tid & 31;
  int wm = w >> 3, wn = w & 7;

  uint32_t lrow = (uint32_t)(lane & 15);
  uint32_t koff = (lane & 16) ? 16u : 0u;
  uint32_t ring = sb + SM_SB + (uint32_t)wn * RING;
  int n0w = wn * 32;

  // per-lane B read offsets (s-invariant swizzle since s*16 rows keep (r>>1)&3 phase)
  uint32_t bsw = (lrow >> 1) & 3;
  uint32_t c0  = (lane & 16) ? 1u : 0u;
  uint32_t boff0 = lrow * 64 + ((c0 ^ bsw) * 16);
  uint32_t boff1 = lrow * 64 + (((c0 + 2) ^ bsw) * 16);

  int ntiles = g_tile_off[TT];
  int w0 = blockIdx.x * chunk;
  int w1 = min(w0 + chunk, ntiles);

  for (int item = w0; item < w1; item++) {
    int t = 0;
    while (item >= g_tile_off[t + 1]) t++;
    int m0 = (item - g_tile_off[t]) * BM;
    int cnt = g_counts[t], base = g_offsets[t];

    __syncthreads();   // all warps done reading prev item's A and B rings

    // ---- B fill: each warp fills rows [wm*128, wm*128+128) of ring wn ----
    {
      #pragma unroll
      for (int j = 0; j < 16; j++) {
        int idx = j * 32 + lane;
        int rl = idx >> 2, c = idx & 3;
        int row = wm * 128 + rl;
        uint32_t dst = ring + (uint32_t)row * 64 +
                       (uint32_t)((c ^ ((row >> 1) & 3)) * 16);
        cp16(dst, &g_B[t][row][n0w + c * 8]);
      }
      asm volatile("cp.async.commit_group;" ::: "memory");
    }

    if (tid >= 256) {
      int k = tid - 256;
      float4 wv;
      wv.x = W1[(t * PMAX + 0) * D + k];
      wv.y = W1[(t * PMAX + 1) * D + k];
      wv.z = W1[(t * PMAX + 2) * D + k];
      wv.w = W1[(t * PMAX + 3) * D + k];
      ((float4*)(smem + SM_W1T))[k] = wv;
      ((float*)(smem + SM_B1))[k] = b1[t * D + k];
    } else if (tid < 128) {
      int gm = m0 + tid; int e = -1, ti = 0;
      float4 xv = {0.f, 0.f, 0.f, 0.f};
      if (gm < cnt) {
        e = g_perm[base + gm];
        ti = type_ids[e] * NSRC + source_ids[e];
        int pc = c_pcount[t];
        float4 p4 = *(const float4*)&params[e * PMAX];
        xv.x = p4.x / c_scales[t][0];
        xv.y = pc > 1 ? p4.y / c_scales[t][1] : 0.f;
        xv.z = pc > 2 ? p4.z / c_scales[t][2] : 0.f;
        xv.w = pc > 3 ? p4.w / c_scales[t][3] : 0.f;
      }
      ((float4*)(smem + SM_XS))[tid] = xv;
      ((int*)(smem + SM_E))[tid]  = e;
      ((int*)(smem + SM_TI))[tid] = ti;
    }
    __syncthreads();   // W1/meta visible

    // ---- A-phase: h = relu(x@W1+b1) -> fp16 smem (128 x 256) ----
    {
      int mg = tid >> 6;              // 0..7 -> rows mg*16..+15
      int kt = tid & 63; int k = kt * 4;
      const float4* w1t = (const float4*)(smem + SM_W1T);
      float4 wa = w1t[k], wb2 = w1t[k + 1], wc = w1t[k + 2], wd = w1t[k + 3];
      float4 bv = *(const float4*)(smem + SM_B1 + (uint32_t)k * 4);
      const float4* xs = (const float4*)(smem + SM_XS);
      #pragma unroll 4
      for (int j = 0; j < 16; j++) {
        int m = mg * 16 + j;
        float4 x = xs[m];
        float h0 = fmaf(x.x, wa.x,  fmaf(x.y, wa.y,  fmaf(x.z, wa.z,  fmaf(x.w, wa.w,  bv.x))));
        float h1 = fmaf(x.x, wb2.x, fmaf(x.y, wb2.y, fmaf(x.z, wb2.z, fmaf(x.w, wb2.w, bv.y))));
        float h2 = fmaf(x.x, wc.x,  fmaf(x.y, wc.y,  fmaf(x.z, wc.z,  fmaf(x.w, wc.w,  bv.z))));
        float h3 = fmaf(x.x, wd.x,  fmaf(x.y, wd.y,  fmaf(x.z, wd.z,  fmaf(x.w, wd.w,  bv.w))));
        h0 = fmaxf(h0, 0.f); h1 = fmaxf(h1, 0.f);
        h2 = fmaxf(h2, 0.f); h3 = fmaxf(h3, 0.f);
        uint32_t hw0, hw1;
        asm("cvt.rn.f16x2.f32 %0, %1, %2;" : "=r"(hw0) : "f"(h1), "f"(h0));
        asm("cvt.rn.f16x2.f32 %0, %1, %2;" : "=r"(hw1) : "f"(h3), "f"(h2));
        *(uint2*)(smem + SM_A + (uint32_t)m * LDAB + (uint32_t)k * 2) = make_uint2(hw0, hw1);
      }
    }
    asm volatile("cp.async.wait_group 0;" ::: "memory");
    __syncthreads();   // A ready + ALL warps' B fills complete

    // ---- mainloop: 16 k16-iters, PURE LDSM + MMA ----
    float acc[4][4][4];
    #pragma unroll
    for (int i = 0; i < 4; i++)
      #pragma unroll
      for (int j = 0; j < 4; j++)
        #pragma unroll
        for (int q = 0; q < 4; q++) acc[i][j][q] = 0.f;

    #pragma unroll 4
    for (int s = 0; s < 16; s++) {
      uint32_t bstep = ring + (uint32_t)s * 1024;
      uint32_t br0[4], br1[4];
      ldm_x4t(br0, bstep + boff0);
      ldm_x4t(br1, bstep + boff1);

      uint32_t ab = sb + SM_A + (uint32_t)s * 32 + koff;
      uint32_t ar[4][4];
      #pragma unroll
      for (int i = 0; i < 4; i++)
        ldm_x4(ar[i], ab + (uint32_t)(wm * 64 + i * 16 + lrow) * LDAB);

      #pragma unroll
      for (int i = 0; i < 4; i++) {
        mma16816(acc[i][0], ar[i], br0[0], br0[1]);
        mma16816(acc[i][1], ar[i], br0[2], br0[3]);
        mma16816(acc[i][2], ar[i], br1[0], br1[1]);
        mma16816(acc[i][3], ar[i], br1[2], br1[3]);
      }
    }

    // ---- epilogue: combined table + relu + scatter ----
    const int* sE  = (const int*)(smem + SM_E);
    const int* sTI = (const int*)(smem + SM_TI);
    #pragma unroll
    for (int i = 0; i < 4; i++) {
      #pragma unroll
      for (int rr = 0; rr < 2; rr++) {
        int ml = wm * 64 + i * 16 + rr * 8 + (lane >> 2);
        int e = sE[ml];
        if (e < 0) continue;
        const float* ts = &g_ts[sTI[ml]][0];
        float* op = out + (size_t)e * D;
        #pragma unroll
        for (int j = 0; j < 4; j++) {
          int col = n0w + j * 8 + (lane & 3) * 2;
          float2 tv = *(const float2*)&ts[col];
          float2 o;
          o.x = fmaxf(acc[i][j][rr * 2 + 0] + tv.x, 0.f);
          o.y = fmaxf(acc[i][j][rr * 2 + 1] + tv.y, 0.f);
          *(float2*)&op[col] = o;
        }
      }
    }
  }
}

// ================= launch =================
extern "C" void kernel_launch(void* const* d_in, const int* in_sizes, int n_in,
                              void* d_out, int out_size) {
  const int*   type_ids     = (const int*)d_in[0];
  const int*   source_ids   = (const int*)d_in[1];
  const float* params       = (const float*)d_in[2];
  const float* type_embed   = (const float*)d_in[3];
  const float* source_embed = (const float*)d_in[4];
  const float* W1           = (const float*)d_in[5];
  const float* b1           = (const float*)d_in[6];
  const float* W2           = (const float*)d_in[7];
  const float* b2           = (const float*)d_in[8];
  const float* Wf           = (const float*)d_in[9];
  const float* bf           = (const float*)d_in[10];
  float* out = (float*)d_out;
  int E = in_sizes[0];
  if (E > E_MAX) E = E_MAX;

  cudaFuncSetAttribute(k_main, cudaFuncAttributeMaxDynamicSharedMemorySize, SM_TOTAL);

  int nb = (E + 1023) / 1024;
  k_hist<<<nb, 256>>>(type_ids, E);
  k_fused<<<317, 256>>>(type_embed, source_embed, b2, Wf, bf, W2, nb);
  k_scatter<<<nb + NTYPES * NSRC, 256>>>(type_ids, E, nb);

  int ntub = (E + BM - 1) / BM + TT;
  int chunk = (ntub + NCTA - 1) / NCTA;
  k_main<<<NCTA, 512, SM_TOTAL>>>(type_ids, source_ids, params, W1, b1, out, chunk);
}

// round 16
// speedup vs baseline: 1.0981x; 1.0981x over previous
#include <cuda_runtime.h>
#include <cuda_fp16.h>
#include <cstdint>

#define D      256
#define TT     9
#define NTYPES 14
#define NSRC   5
#define PMAX   4
#define BM     64
#define E_MAX  131072
#define NBMAX  512
#define NCTA   296

// ---- dynamic SMEM layout (bytes), per CTA ----
#define SM_XS   0                    // 64 x float4         1024
#define SM_E    1024                 // 64 x int             256
#define SM_TI   1280                 // 64 x int             256
#define SM_W1T  1536                 // 256 x float4        4096
#define SM_B1   5632                 // 256 x float         1024
#define SM_A    6656                 // 64 x 528B          33792
#define SM_WB   40448                // 8 warps x 3 stages x 1280B = 30720
#define SM_TOTAL 71168
#define LDAB    528
#define LDBW    80                   // B stage row pitch (conflict-free mod-32)
#define WSTG    1280                 // 16(k) x 80B

__constant__ int   c_base_map[NTYPES] = {0,0,0,1,1,1,2,2,3,4,5,6,7,8};
__constant__ int   c_pcount[TT]       = {2,2,1,1,1,1,3,2,4};
__constant__ float c_scales[TT][PMAX] = {
  {1.f,1e-6f,1.f,1.f},{1.f,1e-6f,1.f,1.f},{1.f,1.f,1.f,1.f},
  {1000.f,1.f,1.f,1.f},{1e-12f,1.f,1.f,1.f},{1e-9f,1.f,1.f,1.f},
  {1.f,1.f,1.f,1.f},{1e-3f,1e-3f,1.f,1.f},{1.f,1.f,1e9f,1.f}
};

// ---- device scratch ----
__device__ int   g_part[NBMAX][TT];
__device__ int   g_bbase[NBMAX][TT];
__device__ int   g_counts[TT];
__device__ int   g_offsets[TT+1];
__device__ int   g_tile_off[TT+1];
__device__ int   g_perm[E_MAX];
__device__ __align__(16) __half g_B[TT][256][256];      // [t][k][n] fp16
__device__ float g_tc[NTYPES][D];
__device__ float g_sc[NSRC][D];
__device__ float g_b2f[TT][D];                          // includes bf
__device__ float g_ts[NTYPES*NSRC][D];                  // combined epilogue table

// ================= PTX helpers =================
__device__ __forceinline__ uint32_t smem_u32(const void* p) {
  uint32_t a;
  asm("{ .reg .u64 t; cvta.to.shared.u64 t, %1; cvt.u32.u64 %0, t; }" : "=r"(a) : "l"(p));
  return a;
}
__device__ __forceinline__ void cp16(uint32_t dst, const void* src) {
  asm volatile("cp.async.cg.shared.global [%0], [%1], 16;" :: "r"(dst), "l"(src) : "memory");
}
__device__ __forceinline__ void ldm_x4(uint32_t* r, uint32_t a) {
  asm volatile("ldmatrix.sync.aligned.m8n8.x4.shared.b16 {%0,%1,%2,%3}, [%4];"
    : "=r"(r[0]),"=r"(r[1]),"=r"(r[2]),"=r"(r[3]) : "r"(a));
}
__device__ __forceinline__ void ldm_x4t(uint32_t* r, uint32_t a) {
  asm volatile("ldmatrix.sync.aligned.m8n8.x4.trans.shared.b16 {%0,%1,%2,%3}, [%4];"
    : "=r"(r[0]),"=r"(r[1]),"=r"(r[2]),"=r"(r[3]) : "r"(a));
}
__device__ __forceinline__ void mma16816(float* c, const uint32_t* a, uint32_t b0, uint32_t b1) {
  asm("mma.sync.aligned.m16n8k16.row.col.f32.f16.f16.f32 "
      "{%0,%1,%2,%3}, {%4,%5,%6,%7}, {%8,%9}, {%0,%1,%2,%3};"
      : "+f"(c[0]),"+f"(c[1]),"+f"(c[2]),"+f"(c[3])
      : "r"(a[0]),"r"(a[1]),"r"(a[2]),"r"(a[3]), "r"(b0),"r"(b1));
}

// ================= launch 0: per-block histogram (4 edges/thread) =================
__global__ void k_hist(const int* __restrict__ type_ids, int E) {
  __shared__ int lh[TT];
  int tid = threadIdx.x, b = blockIdx.x;
  if (tid < TT) lh[tid] = 0;
  __syncthreads();
  int base = (b * 256 + tid) * 4;
  if (base + 3 < E) {
    int4 tv = *(const int4*)&type_ids[base];
    atomicAdd(&lh[c_base_map[tv.x]], 1);
    atomicAdd(&lh[c_base_map[tv.y]], 1);
    atomicAdd(&lh[c_base_map[tv.z]], 1);
    atomicAdd(&lh[c_base_map[tv.w]], 1);
  } else {
    for (int q = 0; q < 4; q++) {
      int e = base + q;
      if (e < E) atomicAdd(&lh[c_base_map[type_ids[e]]], 1);
    }
  }
  __syncthreads();
  if (tid < TT) g_part[b][tid] = lh[tid];
}

// ================= launch 1: fused w2f(8-row blocks) + tables + scan =================
__global__ void k_fused(const float* __restrict__ te, const float* __restrict__ se,
                        const float* __restrict__ b2, const float* __restrict__ Wf,
                        const float* __restrict__ bf, const float* __restrict__ W2,
                        int nb) {
  int bx = blockIdx.x, d = threadIdx.x;
  if (bx < 288) {
    __shared__ float sW2[8][D];
    int t = bx >> 5, kg = bx & 31;
    for (int kk = 0; kk < 8; kk++)
      sW2[kk][d] = W2[(t * D + kg * 8 + kk) * D + d];
    __syncthreads();
    float acc[8];
    #pragma unroll
    for (int kk = 0; kk < 8; kk++) acc[kk] = 0.f;
    const float* wb = Wf + 512 * D + d;
    for (int dp = 0; dp < D; dp++) {
      float wf = wb[dp * D];
      #pragma unroll
      for (int kk = 0; kk < 8; kk++) acc[kk] = fmaf(sW2[kk][dp], wf, acc[kk]);
    }
    #pragma unroll
    for (int kk = 0; kk < 8; kk++)
      g_B[t][kg * 8 + kk][d] = __float2half(acc[kk]);
  } else if (bx < 316) {
    __shared__ float row[D];
    int r = bx - 288;
    const float* src; const float* wbase; float* dst; float acc;
    if (r < NTYPES)             { src = te + r * D;            wbase = Wf;           dst = &g_tc[r][0]; acc = 0.f; }
    else if (r < NTYPES + NSRC) { int s = r - NTYPES; src = se + s * D; wbase = Wf + 256 * D; dst = &g_sc[s][0]; acc = 0.f; }
    else                        { int t = r - NTYPES - NSRC; src = b2 + t * D; wbase = Wf + 512 * D; dst = &g_b2f[t][0]; acc = bf[d]; }
    row[d] = src[d];
    __syncthreads();
    #pragma unroll 8
    for (int k = 0; k < D; k++) acc = fmaf(row[k], wbase[k * D + d], acc);
    dst[d] = acc;
  } else {
    int lane = d & 31, w = d >> 5;
    for (int t = w; t < TT; t += 8) {
      int carry = 0;
      for (int c = 0; c < nb; c += 32) {
        int idx = c + lane;
        int orig = (idx < nb) ? g_part[idx][t] : 0;
        int v = orig;
        #pragma unroll
        for (int sft = 1; sft < 32; sft <<= 1) {
          int u = __shfl_up_sync(0xffffffffu, v, sft);
          if (lane >= sft) v += u;
        }
        if (idx < nb) g_bbase[idx][t] = carry + v - orig;
        carry += __shfl_sync(0xffffffffu, v, 31);
      }
      if (lane == 0) g_counts[t] = carry;
    }
    __syncthreads();
    if (d == 0) {
      int off = 0, toff = 0;
      for (int t = 0; t < TT; t++) {
        g_offsets[t] = off; g_tile_off[t] = toff;
        off += g_counts[t];
        toff += (g_counts[t] + BM - 1) / BM;
      }
      g_offsets[TT] = off; g_tile_off[TT] = toff;
    }
  }
}

// ================= launch 2: scatter (4 edges/thread) + table combine =================
__global__ void k_scatter(const int* __restrict__ type_ids, int E, int nb) {
  int tid = threadIdx.x, b = blockIdx.x;
  if (b >= nb) {
    int r = b - nb, ty = r / NSRC, s = r % NSRC;
    int t = c_base_map[ty];
    g_ts[r][tid] = g_tc[ty][tid] + g_sc[s][tid] + g_b2f[t][tid];
    return;
  }
  __shared__ int lh[TT];
  if (tid < TT) lh[tid] = 0;
  __syncthreads();
  int base = (b * 256 + tid) * 4;
  int tloc[4], lpos[4];
  if (base + 3 < E) {
    int4 tv = *(const int4*)&type_ids[base];
    tloc[0] = c_base_map[tv.x]; tloc[1] = c_base_map[tv.y];
    tloc[2] = c_base_map[tv.z]; tloc[3] = c_base_map[tv.w];
    #pragma unroll
    for (int q = 0; q < 4; q++) lpos[q] = atomicAdd(&lh[tloc[q]], 1);
    #pragma unroll
    for (int q = 0; q < 4; q++)
      g_perm[g_offsets[tloc[q]] + g_bbase[b][tloc[q]] + lpos[q]] = base + q;
  } else {
    for (int q = 0; q < 4; q++) {
      int e = base + q;
      if (e < E) {
        int t = c_base_map[type_ids[e]];
        int lp = atomicAdd(&lh[t], 1);
        g_perm[g_offsets[t] + g_bbase[b][t] + lp] = e;
      }
    }
  }
}

// ================= launch 3: main HMMA kernel =================
// 296 persistent CTAs x 256 threads = 8 warps (1M x 8N), warp tile 64x32,
// 2 CTAs/SM -> two independent instruction streams per SM so one CTA's
// fenced meta/A-phase/epilogue overlaps the other's mainloop.
// Item = 64 edges x 256 N. Per-warp private 3-stage k16 B ring (80B pitch),
// zero block syncs in the mainloop. Same per-edge traffic as the R10 best.
__global__ __launch_bounds__(256, 2) void k_main(
    const int* __restrict__ type_ids, const int* __restrict__ source_ids,
    const float* __restrict__ params, const float* __restrict__ W1,
    const float* __restrict__ b1, float* __restrict__ out, int chunk) {
  extern __shared__ char smem[];
  uint32_t sb = smem_u32(smem);
  int tid = threadIdx.x;
  int w = tid >> 5, lane = tid & 31;
  int wn = w;                        // 8 N-columns, single M group

  uint32_t lrow = (uint32_t)(lane & 15);
  uint32_t koff = (lane & 16) ? 16u : 0u;
  uint32_t wbase = sb + SM_WB + (uint32_t)w * (3 * WSTG);
  uint32_t bfr = (uint32_t)(lane & 15) * LDBW + ((lane & 16) ? 16u : 0u);
  int n0w = wn * 32;

  int cp_kr[2], cp_c16[2];
  #pragma unroll
  for (int j = 0; j < 2; j++) {
    int idx = j * 32 + lane;
    cp_kr[j] = idx >> 2; cp_c16[j] = idx & 3;
  }

  int ntiles = g_tile_off[TT];
  int w0 = blockIdx.x * chunk;
  int w1 = min(w0 + chunk, ntiles);

  for (int item = w0; item < w1; item++) {
    int t = 0;
    while (item >= g_tile_off[t + 1]) t++;
    int m0 = (item - g_tile_off[t]) * BM;
    int cnt = g_counts[t], base = g_offsets[t];

    // per-warp B prefetch stages 0,1
    #pragma unroll
    for (int s = 0; s < 2; s++) {
      #pragma unroll
      for (int j = 0; j < 2; j++) {
        cp16(wbase + (uint32_t)s * WSTG + (uint32_t)cp_kr[j] * LDBW +
               (uint32_t)cp_c16[j] * 16,
             &g_B[t][s * 16 + cp_kr[j]][n0w + cp_c16[j] * 8]);
      }
      asm volatile("cp.async.commit_group;" ::: "memory");
    }

    __syncthreads();   // all warps done with prev item's A/meta

    {
      // W1/b1: all 256 threads; meta: threads 0..63
      int k = tid;
      float4 wv;
      wv.x = W1[(t * PMAX + 0) * D + k];
      wv.y = W1[(t * PMAX + 1) * D + k];
      wv.z = W1[(t * PMAX + 2) * D + k];
      wv.w = W1[(t * PMAX + 3) * D + k];
      ((float4*)(smem + SM_W1T))[k] = wv;
      ((float*)(smem + SM_B1))[k] = b1[t * D + k];
    }
    if (tid < 64) {
      int gm = m0 + tid; int e = -1, ti = 0;
      float4 xv = {0.f, 0.f, 0.f, 0.f};
      if (gm < cnt) {
        e = g_perm[base + gm];
        ti = type_ids[e] * NSRC + source_ids[e];
        int pc = c_pcount[t];
        float4 p4 = *(const float4*)&params[e * PMAX];
        xv.x = p4.x / c_scales[t][0];
        xv.y = pc > 1 ? p4.y / c_scales[t][1] : 0.f;
        xv.z = pc > 2 ? p4.z / c_scales[t][2] : 0.f;
        xv.w = pc > 3 ? p4.w / c_scales[t][3] : 0.f;
      }
      ((float4*)(smem + SM_XS))[tid] = xv;
      ((int*)(smem + SM_E))[tid]  = e;
      ((int*)(smem + SM_TI))[tid] = ti;
    }
    __syncthreads();   // W1/meta visible

    // ---- A-phase: h = relu(x@W1+b1) -> fp16 smem (64 x 256) ----
    {
      int mg = tid >> 6;              // 0..3 -> rows mg*16..+15
      int kt = tid & 63; int k = kt * 4;
      const float4* w1t = (const float4*)(smem + SM_W1T);
      float4 wa = w1t[k], wb2 = w1t[k + 1], wc = w1t[k + 2], wd = w1t[k + 3];
      float4 bv = *(const float4*)(smem + SM_B1 + (uint32_t)k * 4);
      const float4* xs = (const float4*)(smem + SM_XS);
      #pragma unroll 4
      for (int j = 0; j < 16; j++) {
        int m = mg * 16 + j;
        float4 x = xs[m];
        float h0 = fmaf(x.x, wa.x,  fmaf(x.y, wa.y,  fmaf(x.z, wa.z,  fmaf(x.w, wa.w,  bv.x))));
        float h1 = fmaf(x.x, wb2.x, fmaf(x.y, wb2.y, fmaf(x.z, wb2.z, fmaf(x.w, wb2.w, bv.y))));
        float h2 = fmaf(x.x, wc.x,  fmaf(x.y, wc.y,  fmaf(x.z, wc.z,  fmaf(x.w, wc.w,  bv.z))));
        float h3 = fmaf(x.x, wd.x,  fmaf(x.y, wd.y,  fmaf(x.z, wd.z,  fmaf(x.w, wd.w,  bv.w))));
        h0 = fmaxf(h0, 0.f); h1 = fmaxf(h1, 0.f);
        h2 = fmaxf(h2, 0.f); h3 = fmaxf(h3, 0.f);
        uint32_t hw0, hw1;
        asm("cvt.rn.f16x2.f32 %0, %1, %2;" : "=r"(hw0) : "f"(h1), "f"(h0));
        asm("cvt.rn.f16x2.f32 %0, %1, %2;" : "=r"(hw1) : "f"(h3), "f"(h2));
        *(uint2*)(smem + SM_A + (uint32_t)m * LDAB + (uint32_t)k * 2) = make_uint2(hw0, hw1);
      }
    }
    __syncthreads();   // A ready; mainloop is sync-free

    // ---- mainloop: 16 k16-iters, single pass ----
    float acc[4][4][4];
    #pragma unroll
    for (int i = 0; i < 4; i++)
      #pragma unroll
      for (int j = 0; j < 4; j++)
        #pragma unroll
        for (int q = 0; q < 4; q++) acc[i][j][q] = 0.f;

    for (int s = 0; s < 16; s++) {
      asm volatile("cp.async.wait_group 1;" ::: "memory");

      if (s + 2 < 16) {
        int s2 = s + 2;
        uint32_t stg2 = wbase + (uint32_t)(s2 % 3) * WSTG;
        #pragma unroll
        for (int j = 0; j < 2; j++) {
          cp16(stg2 + (uint32_t)cp_kr[j] * LDBW + (uint32_t)cp_c16[j] * 16,
               &g_B[t][s2 * 16 + cp_kr[j]][n0w + cp_c16[j] * 8]);
        }
      }
      asm volatile("cp.async.commit_group;" ::: "memory");

      uint32_t ab = sb + SM_A + (uint32_t)s * 32 + koff;
      uint32_t ar[4][4];
      #pragma unroll
      for (int i = 0; i < 4; i++)
        ldm_x4(ar[i], ab + (uint32_t)(i * 16 + lrow) * LDAB);

      uint32_t bb = wbase + (uint32_t)(s % 3) * WSTG + bfr;
      uint32_t br0[4], br1[4];
      ldm_x4t(br0, bb);
      ldm_x4t(br1, bb + 32);
      #pragma unroll
      for (int i = 0; i < 4; i++) {
        mma16816(acc[i][0], ar[i], br0[0], br0[1]);
        mma16816(acc[i][1], ar[i], br0[2], br0[3]);
        mma16816(acc[i][2], ar[i], br1[0], br1[1]);
        mma16816(acc[i][3], ar[i], br1[2], br1[3]);
      }
    }

    // ---- epilogue: combined table + relu + scatter ----
    const int* sE  = (const int*)(smem + SM_E);
    const int* sTI = (const int*)(smem + SM_TI);
    #pragma unroll
    for (int i = 0; i < 4; i++) {
      #pragma unroll
      for (int rr = 0; rr < 2; rr++) {
        int ml = i * 16 + rr * 8 + (lane >> 2);
        int e = sE[ml];
        if (e < 0) continue;
        const float* ts = &g_ts[sTI[ml]][0];
        float* op = out + (size_t)e * D;
        #pragma unroll
        for (int j = 0; j < 4; j++) {
          int col = n0w + j * 8 + (lane & 3) * 2;
          float2 tv = *(const float2*)&ts[col];
          float2 o;
          o.x = fmaxf(acc[i][j][rr * 2 + 0] + tv.x, 0.f);
          o.y = fmaxf(acc[i][j][rr * 2 + 1] + tv.y, 0.f);
          *(float2*)&op[col] = o;
        }
      }
    }
  }
}

// ================= launch =================
extern "C" void kernel_launch(void* const* d_in, const int* in_sizes, int n_in,
                              void* d_out, int out_size) {
  const int*   type_ids     = (const int*)d_in[0];
  const int*   source_ids   = (const int*)d_in[1];
  const float* params       = (const float*)d_in[2];
  const float* type_embed   = (const float*)d_in[3];
  const float* source_embed = (const float*)d_in[4];
  const float* W1           = (const float*)d_in[5];
  const float* b1           = (const float*)d_in[6];
  const float* W2           = (const float*)d_in[7];
  const float* b2           = (const float*)d_in[8];
  const float* Wf           = (const float*)d_in[9];
  const float* bf           = (const float*)d_in[10];
  float* out = (float*)d_out;
  int E = in_sizes[0];
  if (E > E_MAX) E = E_MAX;

  cudaFuncSetAttribute(k_main, cudaFuncAttributeMaxDynamicSharedMemorySize, SM_TOTAL);

  int nb = (E + 1023) / 1024;
  k_hist<<<nb, 256>>>(type_ids, E);
  k_fused<<<317, 256>>>(type_embed, source_embed, b2, Wf, bf, W2, nb);
  k_scatter<<<nb + NTYPES * NSRC, 256>>>(type_ids, E, nb);

  int ntub = (E + BM - 1) / BM + TT;
  int chunk = (ntub + NCTA - 1) / NCTA;
  k_main<<<NCTA, 256, SM_TOTAL>>>(type_ids, source_ids, params, W1, b1, out, chunk);
}

// round 17
// speedup vs baseline: 1.1225x; 1.0222x over previous
#include <cuda_runtime.h>
#include <cuda_fp16.h>
#include <cstdint>

#define D      256
#define TT     9
#define NTYPES 14
#define NSRC   5
#define PMAX   4
#define BM     64
#define E_MAX  131072
#define NCTA   296

// ---- dynamic SMEM layout (bytes), per CTA ----
#define SM_XS   0                    // 64 x float4         1024
#define SM_E    1024                 // 64 x int             256
#define SM_TI   1280                 // 64 x int             256
#define SM_W1T  1536                 // 256 x float4        4096
#define SM_B1   5632                 // 256 x float         1024
#define SM_A    6656                 // 64 x 528B          33792
#define SM_WB   40448                // 8 warps x 3 stages x 1280B = 30720
#define SM_TOTAL 71168
#define LDAB    528
#define LDBW    80                   // B stage row pitch (conflict-free mod-32)
#define WSTG    1280                 // 16(k) x 80B

__constant__ int   c_base_map[NTYPES] = {0,0,0,1,1,1,2,2,3,4,5,6,7,8};
__constant__ int   c_pcount[TT]       = {2,2,1,1,1,1,3,2,4};
__constant__ float c_scales[TT][PMAX] = {
  {1.f,1e-6f,1.f,1.f},{1.f,1e-6f,1.f,1.f},{1.f,1.f,1.f,1.f},
  {1000.f,1.f,1.f,1.f},{1e-12f,1.f,1.f,1.f},{1e-9f,1.f,1.f,1.f},
  {1.f,1.f,1.f,1.f},{1e-3f,1e-3f,1.f,1.f},{1.f,1.f,1e9f,1.f}
};

// ---- device scratch ----
__device__ int   g_cursor[TT];                          // zero-init; re-zeroed by k_main tail
__device__ int   g_counts[TT];
__device__ int   g_tile_off[TT+1];
__device__ int   g_perm2[TT][E_MAX];                    // fixed-capacity buckets
__device__ __align__(16) __half g_B[TT][256][256];      // [t][k][n] fp16
__device__ float g_tc[NTYPES][D];
__device__ float g_sc[NSRC][D];
__device__ float g_b2f[TT][D];                          // includes bf
__device__ float g_ts[NTYPES*NSRC][D];                  // combined epilogue table

// ================= PTX helpers =================
__device__ __forceinline__ uint32_t smem_u32(const void* p) {
  uint32_t a;
  asm("{ .reg .u64 t; cvta.to.shared.u64 t, %1; cvt.u32.u64 %0, t; }" : "=r"(a) : "l"(p));
  return a;
}
__device__ __forceinline__ void cp16(uint32_t dst, const void* src) {
  asm volatile("cp.async.cg.shared.global [%0], [%1], 16;" :: "r"(dst), "l"(src) : "memory");
}
__device__ __forceinline__ void ldm_x4(uint32_t* r, uint32_t a) {
  asm volatile("ldmatrix.sync.aligned.m8n8.x4.shared.b16 {%0,%1,%2,%3}, [%4];"
    : "=r"(r[0]),"=r"(r[1]),"=r"(r[2]),"=r"(r[3]) : "r"(a));
}
__device__ __forceinline__ void ldm_x4t(uint32_t* r, uint32_t a) {
  asm volatile("ldmatrix.sync.aligned.m8n8.x4.trans.shared.b16 {%0,%1,%2,%3}, [%4];"
    : "=r"(r[0]),"=r"(r[1]),"=r"(r[2]),"=r"(r[3]) : "r"(a));
}
__device__ __forceinline__ void mma16816(float* c, const uint32_t* a, uint32_t b0, uint32_t b1) {
  asm("mma.sync.aligned.m16n8k16.row.col.f32.f16.f16.f32 "
      "{%0,%1,%2,%3}, {%4,%5,%6,%7}, {%8,%9}, {%0,%1,%2,%3};"
      : "+f"(c[0]),"+f"(c[1]),"+f"(c[2]),"+f"(c[3])
      : "r"(a[0]),"r"(a[1]),"r"(a[2]),"r"(a[3]), "r"(b0),"r"(b1));
}

// ================= launch 0: fused scatter ∥ w2f ∥ tables =================
__global__ void k_pre(const int* __restrict__ type_ids, int E, int nb,
                      const float* __restrict__ te, const float* __restrict__ se,
                      const float* __restrict__ b2, const float* __restrict__ Wf,
                      const float* __restrict__ bf, const float* __restrict__ W2) {
  int bx = blockIdx.x, d = threadIdx.x;
  if (bx < nb) {
    // ---- single-pass atomic scatter (order within bucket is arbitrary) ----
    __shared__ int lh[TT];
    __shared__ int lbase[TT];
    if (d < TT) lh[d] = 0;
    __syncthreads();
    int base4 = (bx * 256 + d) * 4;
    int tloc[4], lpos[4], nv = 0;
    if (base4 + 3 < E) {
      int4 tv = *(const int4*)&type_ids[base4];
      tloc[0] = c_base_map[tv.x]; tloc[1] = c_base_map[tv.y];
      tloc[2] = c_base_map[tv.z]; tloc[3] = c_base_map[tv.w];
      nv = 4;
      #pragma unroll
      for (int q = 0; q < 4; q++) lpos[q] = atomicAdd(&lh[tloc[q]], 1);
    } else {
      for (int q = 0; q < 4; q++) {
        int e = base4 + q;
        if (e < E) {
          tloc[nv] = c_base_map[type_ids[e]];
          lpos[nv] = atomicAdd(&lh[tloc[nv]], 1);
          nv++;
        }
      }
    }
    __syncthreads();
    if (d < TT && lh[d]) lbase[d] = atomicAdd(&g_cursor[d], lh[d]);
    __syncthreads();
    for (int q = 0; q < nv; q++)
      g_perm2[tloc[q]][lbase[tloc[q]] + lpos[q]] = base4 + q;
  } else if (bx < nb + 288) {
    // ---- W2f = W2[t] @ Wf[512:768] -> fp16 ; 8 k-rows per block ----
    __shared__ float sW2[8][D];
    int idx = bx - nb;
    int t = idx >> 5, kg = idx & 31;
    for (int kk = 0; kk < 8; kk++)
      sW2[kk][d] = W2[(t * D + kg * 8 + kk) * D + d];
    __syncthreads();
    float acc[8];
    #pragma unroll
    for (int kk = 0; kk < 8; kk++) acc[kk] = 0.f;
    const float* wb = Wf + 512 * D + d;
    for (int dp = 0; dp < D; dp++) {
      float wf = wb[dp * D];
      #pragma unroll
      for (int kk = 0; kk < 8; kk++) acc[kk] = fmaf(sW2[kk][dp], wf, acc[kk]);
    }
    #pragma unroll
    for (int kk = 0; kk < 8; kk++)
      g_B[t][kg * 8 + kk][d] = __float2half(acc[kk]);
  } else {
    // ---- embedding / bias tables ----
    __shared__ float row[D];
    int r = bx - nb - 288;
    const float* src; const float* wbase; float* dst; float acc;
    if (r < NTYPES)             { src = te + r * D;            wbase = Wf;           dst = &g_tc[r][0]; acc = 0.f; }
    else if (r < NTYPES + NSRC) { int s = r - NTYPES; src = se + s * D; wbase = Wf + 256 * D; dst = &g_sc[s][0]; acc = 0.f; }
    else                        { int t = r - NTYPES - NSRC; src = b2 + t * D; wbase = Wf + 512 * D; dst = &g_b2f[t][0]; acc = bf[d]; }
    row[d] = src[d];
    __syncthreads();
    #pragma unroll 8
    for (int k = 0; k < D; k++) acc = fmaf(row[k], wbase[k * D + d], acc);
    dst[d] = acc;
  }
}

// ================= launch 1: scan + table combine =================
__global__ void k_scan() {
  int bx = blockIdx.x, d = threadIdx.x;
  if (bx == 0) {
    if (d == 0) {
      int toff = 0;
      for (int t = 0; t < TT; t++) {
        int c = g_cursor[t];
        g_counts[t] = c;
        g_tile_off[t] = toff;
        toff += (c + BM - 1) / BM;
      }
      g_tile_off[TT] = toff;
    }
  } else {
    int r = bx - 1, ty = r / NSRC, s = r % NSRC;
    int t = c_base_map[ty];
    g_ts[r][d] = g_tc[ty][d] + g_sc[s][d] + g_b2f[t][d];
  }
}

// ================= launch 2: main HMMA kernel (R16 winner) =================
// 296 persistent CTAs x 256 threads = 8 warps (1M x 8N), warp tile 64x32,
// 2 CTAs/SM. Item = 64 edges x 256 N. Per-warp private 3-stage k16 B ring,
// zero block syncs in the mainloop. Tail of block 0 re-zeroes g_cursor for
// the next graph replay.
__global__ __launch_bounds__(256, 2) void k_main(
    const int* __restrict__ type_ids, const int* __restrict__ source_ids,
    const float* __restrict__ params, const float* __restrict__ W1,
    const float* __restrict__ b1, float* __restrict__ out, int chunk) {
  extern __shared__ char smem[];
  uint32_t sb = smem_u32(smem);
  int tid = threadIdx.x;
  int w = tid >> 5, lane = tid & 31;
  int wn = w;

  uint32_t lrow = (uint32_t)(lane & 15);
  uint32_t koff = (lane & 16) ? 16u : 0u;
  uint32_t wbase = sb + SM_WB + (uint32_t)w * (3 * WSTG);
  uint32_t bfr = (uint32_t)(lane & 15) * LDBW + ((lane & 16) ? 16u : 0u);
  int n0w = wn * 32;

  int cp_kr[2], cp_c16[2];
  #pragma unroll
  for (int j = 0; j < 2; j++) {
    int idx = j * 32 + lane;
    cp_kr[j] = idx >> 2; cp_c16[j] = idx & 3;
  }

  int ntiles = g_tile_off[TT];
  int w0 = blockIdx.x * chunk;
  int w1 = min(w0 + chunk, ntiles);

  for (int item = w0; item < w1; item++) {
    int t = 0;
    while (item >= g_tile_off[t + 1]) t++;
    int m0 = (item - g_tile_off[t]) * BM;
    int cnt = g_counts[t];
    const int* bucket = &g_perm2[t][0];

    // per-warp B prefetch stages 0,1
    #pragma unroll
    for (int s = 0; s < 2; s++) {
      #pragma unroll
      for (int j = 0; j < 2; j++) {
        cp16(wbase + (uint32_t)s * WSTG + (uint32_t)cp_kr[j] * LDBW +
               (uint32_t)cp_c16[j] * 16,
             &g_B[t][s * 16 + cp_kr[j]][n0w + cp_c16[j] * 8]);
      }
      asm volatile("cp.async.commit_group;" ::: "memory");
    }

    __syncthreads();   // all warps done with prev item's A/meta

    {
      int k = tid;
      float4 wv;
      wv.x = W1[(t * PMAX + 0) * D + k];
      wv.y = W1[(t * PMAX + 1) * D + k];
      wv.z = W1[(t * PMAX + 2) * D + k];
      wv.w = W1[(t * PMAX + 3) * D + k];
      ((float4*)(smem + SM_W1T))[k] = wv;
      ((float*)(smem + SM_B1))[k] = b1[t * D + k];
    }
    if (tid < 64) {
      int gm = m0 + tid; int e = -1, ti = 0;
      float4 xv = {0.f, 0.f, 0.f, 0.f};
      if (gm < cnt) {
        e = bucket[gm];
        ti = type_ids[e] * NSRC + source_ids[e];
        int pc = c_pcount[t];
        float4 p4 = *(const float4*)&params[e * PMAX];
        xv.x = p4.x / c_scales[t][0];
        xv.y = pc > 1 ? p4.y / c_scales[t][1] : 0.f;
        xv.z = pc > 2 ? p4.z / c_scales[t][2] : 0.f;
        xv.w = pc > 3 ? p4.w / c_scales[t][3] : 0.f;
      }
      ((float4*)(smem + SM_XS))[tid] = xv;
      ((int*)(smem + SM_E))[tid]  = e;
      ((int*)(smem + SM_TI))[tid] = ti;
    }
    __syncthreads();   // W1/meta visible

    // ---- A-phase: h = relu(x@W1+b1) -> fp16 smem (64 x 256) ----
    {
      int mg = tid >> 6;
      int kt = tid & 63; int k = kt * 4;
      const float4* w1t = (const float4*)(smem + SM_W1T);
      float4 wa = w1t[k], wb2 = w1t[k + 1], wc = w1t[k + 2], wd = w1t[k + 3];
      float4 bv = *(const float4*)(smem + SM_B1 + (uint32_t)k * 4);
      const float4* xs = (const float4*)(smem + SM_XS);
      #pragma unroll 4
      for (int j = 0; j < 16; j++) {
        int m = mg * 16 + j;
        float4 x = xs[m];
        float h0 = fmaf(x.x, wa.x,  fmaf(x.y, wa.y,  fmaf(x.z, wa.z,  fmaf(x.w, wa.w,  bv.x))));
        float h1 = fmaf(x.x, wb2.x, fmaf(x.y, wb2.y, fmaf(x.z, wb2.z, fmaf(x.w, wb2.w, bv.y))));
        float h2 = fmaf(x.x, wc.x,  fmaf(x.y, wc.y,  fmaf(x.z, wc.z,  fmaf(x.w, wc.w,  bv.z))));
        float h3 = fmaf(x.x, wd.x,  fmaf(x.y, wd.y,  fmaf(x.z, wd.z,  fmaf(x.w, wd.w,  bv.w))));
        h0 = fmaxf(h0, 0.f); h1 = fmaxf(h1, 0.f);
        h2 = fmaxf(h2, 0.f); h3 = fmaxf(h3, 0.f);
        uint32_t hw0, hw1;
        asm("cvt.rn.f16x2.f32 %0, %1, %2;" : "=r"(hw0) : "f"(h1), "f"(h0));
        asm("cvt.rn.f16x2.f32 %0, %1, %2;" : "=r"(hw1) : "f"(h3), "f"(h2));
        *(uint2*)(smem + SM_A + (uint32_t)m * LDAB + (uint32_t)k * 2) = make_uint2(hw0, hw1);
      }
    }
    __syncthreads();   // A ready; mainloop is sync-free

    // ---- mainloop: 16 k16-iters ----
    float acc[4][4][4];
    #pragma unroll
    for (int i = 0; i < 4; i++)
      #pragma unroll
      for (int j = 0; j < 4; j++)
        #pragma unroll
        for (int q = 0; q < 4; q++) acc[i][j][q] = 0.f;

    for (int s = 0; s < 16; s++) {
      asm volatile("cp.async.wait_group 1;" ::: "memory");

      if (s + 2 < 16) {
        int s2 = s + 2;
        uint32_t stg2 = wbase + (uint32_t)(s2 % 3) * WSTG;
        #pragma unroll
        for (int j = 0; j < 2; j++) {
          cp16(stg2 + (uint32_t)cp_kr[j] * LDBW + (uint32_t)cp_c16[j] * 16,
               &g_B[t][s2 * 16 + cp_kr[j]][n0w + cp_c16[j] * 8]);
        }
      }
      asm volatile("cp.async.commit_group;" ::: "memory");

      uint32_t ab = sb + SM_A + (uint32_t)s * 32 + koff;
      uint32_t ar[4][4];
      #pragma unroll
      for (int i = 0; i < 4; i++)
        ldm_x4(ar[i], ab + (uint32_t)(i * 16 + lrow) * LDAB);

      uint32_t bb = wbase + (uint32_t)(s % 3) * WSTG + bfr;
      uint32_t br0[4], br1[4];
      ldm_x4t(br0, bb);
      ldm_x4t(br1, bb + 32);
      #pragma unroll
      for (int i = 0; i < 4; i++) {
        mma16816(acc[i][0], ar[i], br0[0], br0[1]);
        mma16816(acc[i][1], ar[i], br0[2], br0[3]);
        mma16816(acc[i][2], ar[i], br1[0], br1[1]);
        mma16816(acc[i][3], ar[i], br1[2], br1[3]);
      }
    }

    // ---- epilogue ----
    const int* sE  = (const int*)(smem + SM_E);
    const int* sTI = (const int*)(smem + SM_TI);
    #pragma unroll
    for (int i = 0; i < 4; i++) {
      #pragma unroll
      for (int rr = 0; rr < 2; rr++) {
        int ml = i * 16 + rr * 8 + (lane >> 2);
        int e = sE[ml];
        if (e < 0) continue;
        const float* ts = &g_ts[sTI[ml]][0];
        float* op = out + (size_t)e * D;
        #pragma unroll
        for (int j = 0; j < 4; j++) {
          int col = n0w + j * 8 + (lane & 3) * 2;
          float2 tv = *(const float2*)&ts[col];
          float2 o;
          o.x = fmaxf(acc[i][j][rr * 2 + 0] + tv.x, 0.f);
          o.y = fmaxf(acc[i][j][rr * 2 + 1] + tv.y, 0.f);
          *(float2*)&op[col] = o;
        }
      }
    }
  }

  // reset cursors for the next graph replay (dead after k_scan this run)
  if (blockIdx.x == 0 && tid < TT) g_cursor[tid] = 0;
}

// ================= launch =================
extern "C" void kernel_launch(void* const* d_in, const int* in_sizes, int n_in,
                              void* d_out, int out_size) {
  const int*   type_ids     = (const int*)d_in[0];
  const int*   source_ids   = (const int*)d_in[1];
  const float* params       = (const float*)d_in[2];
  const float* type_embed   = (const float*)d_in[3];
  const float* source_embed = (const float*)d_in[4];
  const float* W1           = (const float*)d_in[5];
  const float* b1           = (const float*)d_in[6];
  const float* W2           = (const float*)d_in[7];
  const float* b2           = (const float*)d_in[8];
  const float* Wf           = (const float*)d_in[9];
  const float* bf           = (const float*)d_in[10];
  float* out = (float*)d_out;
  int E = in_sizes[0];
  if (E > E_MAX) E = E_MAX;

  cudaFuncSetAttribute(k_main, cudaFuncAttributeMaxDynamicSharedMemorySize, SM_TOTAL);

  int nb = (E + 1023) / 1024;
  k_pre<<<nb + 288 + 28, 256>>>(type_ids, E, nb, type_embed, source_embed,
                                b2, Wf, bf, W2);
  k_scan<<<1 + NTYPES * NSRC, 256>>>();

  int ntub = (E + BM - 1) / BM + TT;
  int chunk = (ntub + NCTA - 1) / NCTA;
  k_main<<<NCTA, 256, SM_TOTAL>>>(type_ids, source_ids, params, W1, b1, out, chunk);
}